// round 7
// baseline (speedup 1.0000x reference)
#include <cuda_runtime.h>
#include <cuda_fp16.h>
#include <math.h>
#include <stdint.h>

#define D_DIM 128
#define K_DIM 512
#define TMROWS 64
#define NTHREADS 256
#define SOFTMIN_BETA 10.0f

#define DSTRIDE 516                         // s_dist row stride (floats)
#define LSTR 132                            // s_lat fp32 row stride (floats)
#define RSTRIDE 272                         // fp16 tile row stride (bytes)
#define ASZ (64 * RSTRIDE)                  // 17408 per A split
#define BSZ (32 * RSTRIDE)                  // 8704 per B buffer
#define OFF_LAT  (TMROWS * DSTRIDE * 4)     // 132096
#define OFF_A    (OFF_LAT + 64 * LSTR * 4)  // 165888
#define OFF_B    (OFF_A + 2 * ASZ)          // 200704
#define OFF_TAIL (OFF_B + 2 * BSZ)          // 218112
#define SMEM_BYTES (OFF_TAIL + 2304)        // 220416

// ---------------- device globals (zero-initialized at load; fin resets them) ----------------
__device__ double g_sq_sum;
__device__ double g_mind_sum;
__device__ unsigned int g_counts[K_DIM];

// ---------------- PTX helpers (baseline PTX only: plain sm_103 target) ----------------
__device__ __forceinline__ uint32_t smem_to_u32(const void* p) {
    uint32_t a;
    asm("{ .reg .u64 t; cvta.to.shared.u64 t, %1; cvt.u32.u64 %0, t; }" : "=r"(a) : "l"(p));
    return a;
}
#define LDSM_X4(r0, r1, r2, r3, addr) \
    asm volatile("ldmatrix.sync.aligned.m8n8.x4.shared.b16 {%0,%1,%2,%3}, [%4];" \
                 : "=r"(r0), "=r"(r1), "=r"(r2), "=r"(r3) : "r"(addr))

__device__ __forceinline__ void mma16816(float* c, const uint32_t* a, uint32_t b0, uint32_t b1) {
    asm volatile(
        "mma.sync.aligned.m16n8k16.row.col.f32.f16.f16.f32 "
        "{%0,%1,%2,%3}, {%4,%5,%6,%7}, {%8,%9}, {%0,%1,%2,%3};"
        : "+f"(c[0]), "+f"(c[1]), "+f"(c[2]), "+f"(c[3])
        : "r"(a[0]), "r"(a[1]), "r"(a[2]), "r"(a[3]), "r"(b0), "r"(b1));
}

// ---------------- main kernel (FIRST graph node -> finally profiled) ----------------
__global__ void __launch_bounds__(NTHREADS) vq_main_kernel(
    const float* __restrict__ latents,
    const float* __restrict__ emb,
    float* __restrict__ out_q,
    float* __restrict__ out_ind,
    float* __restrict__ out_soft)
{
    extern __shared__ __align__(16) unsigned char smem[];
    float* s_dist  = (float*)smem;                       // 64 x DSTRIDE
    float* s_lat   = (float*)(smem + OFF_LAT);           // 64 x LSTR fp32 (exact)
    unsigned char* s_a = smem + OFF_A;                   // 2 fp16 splits x 64 x RSTRIDE
    unsigned char* s_b = smem + OFF_B;                   // 2 buffers x 32 x RSTRIDE
    float* s_esq   = (float*)(smem + OFF_TAIL);          // 512 (approx, softmax only)
    float* s_rowsq = s_esq + K_DIM;                      // 64 (exact chains)

    const int tid = threadIdx.x;
    const int wid = tid >> 5, lane = tid & 31;
    const long long row0 = (long long)blockIdx.x * TMROWS;
    const uint32_t sbase = smem_to_u32(smem);

    // --- stage latents: fp32 (exact) + fp16 2-split tiles ---
    {
        const float4* g = (const float4*)(latents + row0 * D_DIM);
#pragma unroll
        for (int it = 0; it < 8; ++it) {
            int idx = it * NTHREADS + tid;
            int row = idx >> 5, c4 = idx & 31;
            float4 x = g[idx];
            *(float4*)(s_lat + row * LSTR + c4 * 4) = x;
            __half a0x = __float2half_rn(x.x), a0y = __float2half_rn(x.y);
            __half a0z = __float2half_rn(x.z), a0w = __float2half_rn(x.w);
            __half a1x = __float2half_rn(x.x - __half2float(a0x));
            __half a1y = __float2half_rn(x.y - __half2float(a0y));
            __half a1z = __float2half_rn(x.z - __half2float(a0z));
            __half a1w = __float2half_rn(x.w - __half2float(a0w));
            union { __half2 h[2]; unsigned long long u; } u0, u1;
            u0.h[0] = __halves2half2(a0x, a0y); u0.h[1] = __halves2half2(a0z, a0w);
            u1.h[0] = __halves2half2(a1x, a1y); u1.h[1] = __halves2half2(a1z, a1w);
            *(unsigned long long*)(s_a + 0 * ASZ + row * RSTRIDE + c4 * 8) = u0.u;
            *(unsigned long long*)(s_a + 1 * ASZ + row * RSTRIDE + c4 * 8) = u1.u;
        }
    }

    // --- preload B chunk 0 (32 emb rows fp32) ---
    const float4* eb = (const float4*)emb;
    const int brow = tid >> 3, bdb = tid & 7;
    float4 v[4];
#pragma unroll
    for (int j = 0; j < 4; ++j) v[j] = eb[(size_t)brow * 32 + bdb * 4 + j];

    __syncthreads();

    // --- rowsq: exact sequential reference chains (from exact s_lat) ---
    if (tid < TMROWS) {
        const float* lr = s_lat + tid * LSTR;
        float s = 0.f;
        for (int d = 0; d < D_DIM; ++d)
            s = __fadd_rn(s, __fmul_rn(lr[d], lr[d]));
        s_rowsq[tid] = s;
    }

    // --- fragment addresses (mapping validated in round 6) ---
    const int mbase = (wid & 3) * 16;
    const int nhalf = wid >> 2;
    const int sel = lane >> 3, l7 = lane & 7;
    const uint32_t aAddr = sbase + OFF_A
        + (uint32_t)((mbase + (sel & 1) * 8 + l7) * RSTRIDE + (sel >> 1) * 16);
    const uint32_t bOff =
        (uint32_t)((nhalf * 16 + (sel >> 1) * 8 + l7) * RSTRIDE + (sel & 1) * 16);
    const int r1 = mbase + (lane >> 2), r2 = r1 + 8;

    // ---- GEMM over 16 n-chunks of 32 cols (fp16 2-pass: a0*b + a1*b) ----
    for (int c = 0; c < 16; ++c) {
        unsigned char* sb = s_b + (c & 1) * BSZ;
        {
            // convert & store B fp16; approx esq (softmax only)
            union { __half2 h[4]; uint4 u; } p0, p1;
            p0.h[0] = __floats2half2_rn(v[0].x, v[0].y);
            p0.h[1] = __floats2half2_rn(v[0].z, v[0].w);
            p0.h[2] = __floats2half2_rn(v[1].x, v[1].y);
            p0.h[3] = __floats2half2_rn(v[1].z, v[1].w);
            p1.h[0] = __floats2half2_rn(v[2].x, v[2].y);
            p1.h[1] = __floats2half2_rn(v[2].z, v[2].w);
            p1.h[2] = __floats2half2_rn(v[3].x, v[3].y);
            p1.h[3] = __floats2half2_rn(v[3].z, v[3].w);
            *(uint4*)(sb + brow * RSTRIDE + bdb * 32) = p0.u;
            *(uint4*)(sb + brow * RSTRIDE + bdb * 32 + 16) = p1.u;
            float q = 0.f;
#pragma unroll
            for (int j = 0; j < 4; ++j)
                q += v[j].x * v[j].x + v[j].y * v[j].y + v[j].z * v[j].z + v[j].w * v[j].w;
            q += __shfl_xor_sync(0xffffffffu, q, 1);
            q += __shfl_xor_sync(0xffffffffu, q, 2);
            q += __shfl_xor_sync(0xffffffffu, q, 4);
            if (bdb == 0) s_esq[c * 32 + brow] = q;
        }
        __syncthreads();
        if (c < 15) {
#pragma unroll
            for (int j = 0; j < 4; ++j)
                v[j] = eb[(size_t)((c + 1) * 32 + brow) * 32 + bdb * 4 + j];
        }

        float acc0[4] = {0, 0, 0, 0}, acc1[4] = {0, 0, 0, 0};
        const uint32_t bAddr = sbase + OFF_B + (uint32_t)((c & 1) * BSZ) + bOff;
#pragma unroll
        for (int kc = 0; kc < 8; ++kc) {
            uint32_t A0[4], A1[4], Bf[4];
            uint32_t ko = (uint32_t)(kc * 32);
            LDSM_X4(A0[0], A0[1], A0[2], A0[3], aAddr + ko);
            LDSM_X4(A1[0], A1[1], A1[2], A1[3], aAddr + ASZ + ko);
            LDSM_X4(Bf[0], Bf[1], Bf[2], Bf[3], bAddr + ko);
            mma16816(acc0, A0, Bf[0], Bf[1]);
            mma16816(acc0, A1, Bf[0], Bf[1]);
            mma16816(acc1, A0, Bf[2], Bf[3]);
            mma16816(acc1, A1, Bf[2], Bf[3]);
        }

        // approx dist = fl( fl(rowsq+esq) - 2*dot ) into smem
        {
            float rs1 = s_rowsq[r1], rs2 = s_rowsq[r2];
            int ng = c * 32 + nhalf * 16 + (lane & 3) * 2;
            float2 es = *(const float2*)(s_esq + ng);
            float2 dA, dB;
            dA.x = __fmaf_rn(-2.f, acc0[0], __fadd_rn(rs1, es.x));
            dA.y = __fmaf_rn(-2.f, acc0[1], __fadd_rn(rs1, es.y));
            dB.x = __fmaf_rn(-2.f, acc0[2], __fadd_rn(rs2, es.x));
            dB.y = __fmaf_rn(-2.f, acc0[3], __fadd_rn(rs2, es.y));
            *(float2*)(s_dist + r1 * DSTRIDE + ng) = dA;
            *(float2*)(s_dist + r2 * DSTRIDE + ng) = dB;
            float2 es2 = *(const float2*)(s_esq + ng + 8);
            dA.x = __fmaf_rn(-2.f, acc1[0], __fadd_rn(rs1, es2.x));
            dA.y = __fmaf_rn(-2.f, acc1[1], __fadd_rn(rs1, es2.y));
            dB.x = __fmaf_rn(-2.f, acc1[2], __fadd_rn(rs2, es2.x));
            dB.y = __fmaf_rn(-2.f, acc1[3], __fadd_rn(rs2, es2.y));
            *(float2*)(s_dist + r1 * DSTRIDE + ng + 8) = dA;
            *(float2*)(s_dist + r2 * DSTRIDE + ng + 8) = dB;
        }
        __syncthreads();
    }

    // ---- epilogue: approx-min -> exact rescue (ref grid) -> softmax -> outputs ----
    float warp_sq = 0.f, warp_cm = 0.f;

#pragma unroll 1
    for (int i = 0; i < 8; ++i) {
        int r = wid * 8 + i;
        const float* dr = s_dist + r * DSTRIDE;

        float dv[16];
        float bv = 3.4e38f;
#pragma unroll
        for (int t = 0; t < 16; ++t) {
            float x = dr[lane + 32 * t];
            dv[t] = x;
            bv = fminf(bv, x);
        }
#pragma unroll
        for (int o = 16; o; o >>= 1)
            bv = fminf(bv, __shfl_xor_sync(0xffffffffu, bv, o));

        // rescue: exact dot AND exact embsq chains per candidate (reference grid)
        const float margin = 3e-4f;
        const float rsq = s_rowsq[r];
        const float* lrow = s_lat + r * LSTR;     // exact fp32 latent row (smem bcast)
        float bestd = 3.4e38f;
        int bestk = 0x7fffffff;
#pragma unroll 1
        for (int t = 0; t < 16; ++t) {
            if (dv[t] <= bv + margin) {
                int k = lane + 32 * t;
                const float* er = emb + (size_t)k * D_DIM;
                float a = 0.f, q = 0.f;
                for (int d = 0; d < D_DIM; ++d) {
                    float ev = er[d];
                    a = __fmaf_rn(lrow[d], ev, a);
                    q = __fadd_rn(q, __fmul_rn(ev, ev));
                }
                float de = __fmaf_rn(-2.f, a, __fadd_rn(rsq, q));
                if (de < bestd || (de == bestd && k < bestk)) { bestd = de; bestk = k; }
            }
        }
#pragma unroll
        for (int o = 16; o; o >>= 1) {
            float od = __shfl_xor_sync(0xffffffffu, bestd, o);
            int   ok = __shfl_xor_sync(0xffffffffu, bestk, o);
            if (od < bestd || (od == bestd && ok < bestk)) { bestd = od; bestk = ok; }
        }

        long long rg = row0 + r;
        if (lane == 0) {
            atomicAdd(&g_counts[bestk], 1u);
            out_ind[rg] = (float)bestk;
            warp_cm += bestd;
        }

        // softmax(-beta*dist) from approx dist
        float ev[16], sum = 0.f;
#pragma unroll
        for (int t = 0; t < 16; ++t) {
            float e = __expf(-SOFTMIN_BETA * (dv[t] - bv));
            ev[t] = e;
            sum += e;
        }
#pragma unroll
        for (int o = 16; o; o >>= 1) sum += __shfl_xor_sync(0xffffffffu, sum, o);
        float inv = 1.0f / sum;
        float* os = out_soft + rg * K_DIM;
#pragma unroll
        for (int t = 0; t < 16; ++t) os[lane + 32 * t] = ev[t] * inv;

        // quantized + loss accumulation
        float4 qv = ((const float4*)emb)[bestk * 32 + lane];
        float4 lv = *(const float4*)(s_lat + r * LSTR + 4 * lane);
        ((float4*)(out_q + rg * D_DIM))[lane] = qv;
        float dx = qv.x - lv.x, dy = qv.y - lv.y, dz = qv.z - lv.z, dw = qv.w - lv.w;
        float sq = dx * dx + dy * dy + dz * dz + dw * dw;
#pragma unroll
        for (int o = 16; o; o >>= 1) sq += __shfl_xor_sync(0xffffffffu, sq, o);
        if (lane == 0) warp_sq += sq;
    }

    if (lane == 0) {
        atomicAdd(&g_sq_sum, (double)warp_sq);
        atomicAdd(&g_mind_sum, (double)warp_cm);
    }
}

// ---------------- finalize: scalars; then RESET globals for the next call ----------------
__global__ void vq_fin_kernel(float* __restrict__ out_vq,
                              float* __restrict__ out_ent,
                              float* __restrict__ out_cm,
                              long long B)
{
    __shared__ float red[K_DIM];
    int k = threadIdx.x;   // 512 threads
    float p = (float)g_counts[k] / (float)B;
    red[k] = -p * logf(p + 1e-10f);
    g_counts[k] = 0u;      // reset for next call
    __syncthreads();
    for (int s = K_DIM / 2; s > 0; s >>= 1) {
        if (k < s) red[k] += red[k + s];
        __syncthreads();
    }
    if (k == 0) {
        double bd = (double)B;
        out_vq[0]  = (float)((g_sq_sum / (bd * (double)D_DIM)) * 1.25);
        out_ent[0] = red[0];
        out_cm[0]  = (float)(g_mind_sum / bd);
        g_sq_sum = 0.0;
        g_mind_sum = 0.0;
    }
}

extern "C" void kernel_launch(void* const* d_in, const int* in_sizes, int n_in,
                              void* d_out, int out_size)
{
    const float* latents = (const float*)d_in[0];
    const float* emb     = (const float*)d_in[1];
    long long B = (long long)in_sizes[0] / D_DIM;

    float* out      = (float*)d_out;
    float* out_q    = out;
    float* out_vq   = out + B * D_DIM;
    float* out_ent  = out_vq + 1;
    float* out_ind  = out_ent + 1;
    float* out_soft = out_ind + B;
    float* out_cm   = out_soft + B * K_DIM;

    cudaFuncSetAttribute(vq_main_kernel, cudaFuncAttributeMaxDynamicSharedMemorySize, SMEM_BYTES);

    vq_main_kernel<<<(unsigned)(B / TMROWS), NTHREADS, SMEM_BYTES>>>(latents, emb, out_q, out_ind, out_soft);
    vq_fin_kernel<<<1, K_DIM>>>(out_vq, out_ent, out_cm, B);
}